// round 9
// baseline (speedup 1.0000x reference)
#include <cuda_runtime.h>
#include <cuda_bf16.h>
#include <cstdint>

#define TT   4096   // sequence length T
#define EE   256    // embedding dim
#define HH   256    // hidden
#define LL   18     // labels
#define NG   1024   // 4*H gate rows
#define CS   8      // cluster size (CTAs per direction)
#define UPC  32     // hidden units per CTA
#define NEGV -10000.0f
#define STARTL 16
#define STOPL  17
#define TPB  32     // timesteps per pre tile
#define NTILE (TT / TPB)        // 128 tiles per direction
#define LSTM_BLOCKS (2 * CS)    // 16
#define PRE_BLOCKS  (2 * NTILE) // 256
#define HBUF 288    // padded h buffer: slice k at word 36k (bank spread)
#define IDXH(u) ((u) + ((((unsigned)(u)) >> 5) << 2))

typedef unsigned long long ull;

// ---------------- scratch (static device globals; no runtime alloc) --------
__device__ float g_pre[2][(size_t)TT * NG];   // precomputed x@w_ih.T + b
__device__ float g_hs[2][(size_t)TT * HH];    // hidden states (fwd, bwd)
__device__ float g_emit[(size_t)TT * LL];
__device__ int   g_pflag[2][NTILE];           // tile-ready flags (cleared by viterbi)

// ---------------- helpers --------------------------------------------------
__device__ __forceinline__ float tanh_ap(float x) {        // MUFU.TANH
    float y; asm("tanh.approx.f32 %0, %1;" : "=f"(y) : "f"(x)); return y;
}
__device__ __forceinline__ float sigf(float x) {           // 1 MUFU + 1 FMA
    return fmaf(0.5f, tanh_ap(0.5f * x), 0.5f);
}
__device__ __forceinline__ uint32_t smem_u32(const void* p) {
    uint32_t a;
    asm("{ .reg .u64 t; cvta.to.shared.u64 t, %1; cvt.u32.u64 %0, t; }"
        : "=r"(a) : "l"(p));
    return a;
}
__device__ __forceinline__ uint32_t mapa_rank(uint32_t laddr, uint32_t rank) {
    uint32_t r;
    asm("mapa.shared::cluster.u32 %0, %1, %2;" : "=r"(r) : "r"(laddr), "r"(rank));
    return r;
}
__device__ __forceinline__ void st_async_v2b64(uint32_t raddr, ull a, ull b,
                                               uint32_t rmbar) {
    asm volatile(
        "st.async.shared::cluster.mbarrier::complete_tx::bytes.v2.b64 "
        "[%0], {%1, %2}, [%3];"
        :: "r"(raddr), "l"(a), "l"(b), "r"(rmbar) : "memory");
}
__device__ __forceinline__ void mbar_init(uint32_t addr, uint32_t cnt) {
    asm volatile("mbarrier.init.shared.b64 [%0], %1;" :: "r"(addr), "r"(cnt) : "memory");
}
__device__ __forceinline__ void mbar_expect_tx(uint32_t addr, uint32_t bytes) {
    asm volatile("mbarrier.arrive.expect_tx.shared.b64 _, [%0], %1;"
                 :: "r"(addr), "r"(bytes) : "memory");
}
__device__ __forceinline__ void mbar_wait(uint32_t addr, uint32_t parity) {
    uint32_t done;
    asm volatile(
        "{\n\t.reg .pred p;\n\t"
        "mbarrier.try_wait.parity.acquire.cluster.shared::cta.b64 p, [%1], %2;\n\t"
        "selp.b32 %0, 1, 0, p;\n\t}"
        : "=r"(done) : "r"(addr), "r"(parity) : "memory");
    while (!done) {
        asm volatile(
            "{\n\t.reg .pred p;\n\t"
            "mbarrier.try_wait.parity.acquire.cluster.shared::cta.b64 p, [%1], %2, 0x989680;\n\t"
            "selp.b32 %0, 1, 0, p;\n\t}"
            : "=r"(done) : "r"(addr), "r"(parity) : "memory");
    }
}
__device__ __forceinline__ ull pack2(float x, float y) {
    ull d; asm("mov.b64 %0, {%1, %2};" : "=l"(d) : "f"(x), "f"(y)); return d;
}
__device__ __forceinline__ void unpack2(float& lo, float& hi, ull a) {
    asm("mov.b64 {%0, %1}, %2;" : "=f"(lo), "=f"(hi) : "l"(a));
}
__device__ __forceinline__ void fma2(ull& d, ull a, ull b) {
    asm("fma.rn.f32x2 %0, %1, %2, %0;" : "+l"(d) : "l"(a), "l"(b));
}
__device__ __forceinline__ void st_rel_sh(uint32_t addr, int v) {
    asm volatile("st.release.cta.shared.b32 [%0], %1;" :: "r"(addr), "r"(v) : "memory");
}
__device__ __forceinline__ int ld_acq_sh(uint32_t addr) {
    int v;
    asm volatile("ld.acquire.cta.shared.b32 %0, [%1];" : "=r"(v) : "r"(addr) : "memory");
    return v;
}
__device__ __forceinline__ int ld_rlx_sh(uint32_t addr) {
    int v;
    asm volatile("ld.relaxed.cta.shared.b32 %0, [%1];" : "=r"(v) : "r"(addr) : "memory");
    return v;
}
__device__ __forceinline__ int ld_acq_gpu(const int* p) {
    int v;
    asm volatile("ld.acquire.gpu.b32 %0, [%1];" : "=r"(v) : "l"(p) : "memory");
    return v;
}
__device__ __forceinline__ void wait_tile(int dir, int c) {
    while (!ld_acq_gpu(&g_pflag[dir][c])) { }
}

// ---------------- fused kernel shared memory -------------------------------
__shared__ union FusedSmem {
    struct { float sh_h[2][HBUF]; ull smbar[2]; } l;     // lstm blocks
    float xs[TPB][EE];                                    // producer blocks
} s_u;

// ---------------- producer body: pre[d][t][row] for one 32-step tile -------
__device__ void pre_body(int p,
    const int* __restrict__ feats, const float* __restrict__ emb,
    const float* __restrict__ w_f, const float* __restrict__ b_f,
    const float* __restrict__ w_b, const float* __restrict__ b_b)
{
    const int tid = threadIdx.x;
    const int dir = p >> 7;
    const int c   = p & (NTILE - 1);               // consumption-order tile
    const int t0  = dir ? (TT - TPB - c * TPB) : c * TPB;
    const float* w  = dir ? w_b : w_f;
    const float* bb = dir ? b_b : b_f;
    float* pre = g_pre[dir];
    float (*xs)[EE] = s_u.xs;

    {   // gather TPB embedding rows into shared (8 threads per row)
        int i = tid >> 3, cc0 = tid & 7;
        int f = feats[t0 + i];
        const float4* src = (const float4*)(emb + (size_t)f * EE);
        #pragma unroll
        for (int cc = 0; cc < 8; ++cc)
            ((float4*)xs[i])[cc0 + cc * 8] = __ldg(src + cc0 + cc * 8);
    }
    __syncthreads();

    for (int q = 0; q < 4; ++q) {
        const int row = q * 256 + tid;
        const float4* wp = (const float4*)(w + (size_t)row * EE);
        const float bv = __ldg(&bb[row]);
        float acc[TPB];
        #pragma unroll
        for (int i = 0; i < TPB; ++i) acc[i] = bv;
        for (int k4 = 0; k4 < 64; ++k4) {
            float4 wv = __ldg(wp + k4);
            #pragma unroll
            for (int i = 0; i < TPB; ++i) {
                float4 xv = *(const float4*)&xs[i][k4 * 4];
                acc[i] = fmaf(wv.x, xv.x, acc[i]);
                acc[i] = fmaf(wv.y, xv.y, acc[i]);
                acc[i] = fmaf(wv.z, xv.z, acc[i]);
                acc[i] = fmaf(wv.w, xv.w, acc[i]);
            }
        }
        #pragma unroll
        for (int i = 0; i < TPB; ++i)
            pre[(size_t)(t0 + i) * NG + row] = acc[i];
    }

    __syncthreads();
    if (tid == 0) {
        __threadfence();
        asm volatile("st.release.gpu.b32 [%0], %1;"
                     :: "l"(&g_pflag[dir][c]), "r"(1) : "memory");
    }
}

// ---------------- LSTM body: 2 clusters of 8 CTAs (blocks 0..15) ------------
__device__ void lstm_body(const float* __restrict__ whh_f,
                          const float* __restrict__ whh_b)
{
    float (*sh_h)[HBUF] = s_u.l.sh_h;
    ull* smbar = s_u.l.smbar;

    const int tid = threadIdx.x;
    const int dir = blockIdx.x / CS;
    uint32_t rank;
    asm("mov.u32 %0, %%cluster_ctarank;" : "=r"(rank));

    const int w = tid >> 5, l = tid & 31;
    const int kq   = l & 7;                 // k-slice: h[kq*32 .. +32)
    const int ugrp = w * 4 + (l >> 3);      // unit local 0..31
    const int unit_global = (int)rank * UPC + ugrp;
    const bool k0 = (kq == 0);
    const int ug4 = (int)rank * UPC + w * 4;   // warp's 4-unit group base

    // weights: 4 gate rows of this unit, cols [kq*32, +32) as f32x2 pairs
    const float* whh = dir ? whh_b : whh_f;
    ull w2[4][16];
    #pragma unroll
    for (int g = 0; g < 4; ++g) {
        const float4* wp = (const float4*)(whh + (size_t)(g * HH + unit_global) * HH + kq * 32);
        #pragma unroll
        for (int m = 0; m < 8; ++m) {
            float4 f = __ldg(wp + m);
            w2[g][2 * m]     = pack2(f.x, f.y);
            w2[g][2 * m + 1] = pack2(f.z, f.w);
        }
    }

    // publish targets: k0 lane (l>>3 = j) sends warp's 16B group to 2 ranks
    const int j2 = (l >> 3) * 2;
    const uint32_t loc_b = smem_u32(&smbar[0]);
    uint32_t remh[2][2], remb[2][2];
    #pragma unroll
    for (int s = 0; s < 2; ++s) {
        const uint32_t locp = smem_u32(&sh_h[s][IDXH(ug4)]);
        #pragma unroll
        for (int i = 0; i < 2; ++i) {
            remh[s][i] = mapa_rank(locp, j2 + i);
            remb[s][i] = mapa_rank(loc_b + s * 8, j2 + i);
        }
    }

    for (int i = tid; i < 2 * HBUF; i += 256) ((float*)sh_h)[i] = 0.f;
    if (tid == 0) { mbar_init(loc_b, 1); mbar_init(loc_b + 8, 1); }
    __syncthreads();
    asm volatile("barrier.cluster.arrive.aligned;" ::: "memory");
    asm volatile("barrier.cluster.wait.aligned;" ::: "memory");

    const float* pre = g_pre[dir];
    float* hs = g_hs[dir];
    float c = 0.f;

    auto tmap = [&](int n) { return dir ? (TT - 1 - n) : n; };
    float p0[4], p1[4];
    #pragma unroll
    for (int g = 0; g < 4; ++g) { p0[g] = 0.f; p1[g] = 0.f; }
    if (k0) {
        wait_tile(dir, 0);                       // producer handshake
        #pragma unroll
        for (int g = 0; g < 4; ++g) {
            p0[g] = __ldcg(&pre[(size_t)tmap(0) * NG + g * HH + unit_global]);
            p1[g] = __ldcg(&pre[(size_t)tmap(1) * NG + g * HH + unit_global]);
        }
    }

    for (int n = 0; n < TT; ++n) {
        const int tstep = tmap(n);
        if (tid == 0) mbar_expect_tx(loc_b + (n & 1) * 8, CS * UPC * 4);
        if (n > 0) mbar_wait(loc_b + ((n - 1) & 1) * 8, ((n - 1) >> 1) & 1);

        float p2[4] = {0.f, 0.f, 0.f, 0.f};
        if (k0 && n + 2 < TT) {
            if (((n + 2) & (TPB - 1)) == 0)
                wait_tile(dir, (n + 2) >> 5);    // next tile ready?
            #pragma unroll
            for (int g = 0; g < 4; ++g)
                p2[g] = __ldcg(&pre[(size_t)tmap(n + 2) * NG + g * HH + unit_global]);
        }

        // ---- load my 32-float h slice (broadcast x4 across lanes) ---------
        const ulonglong2* hp =
            (const ulonglong2*)((const char*)sh_h[(n + 1) & 1] + kq * 144);
        ull h2[16];
        #pragma unroll
        for (int j = 0; j < 8; ++j) {
            ulonglong2 v = hp[j];
            h2[2 * j] = v.x; h2[2 * j + 1] = v.y;
        }

        // ---- 4 gate partial dots over the slice ---------------------------
        float s[4];
        #pragma unroll
        for (int g = 0; g < 4; ++g) {
            ull a = 0ull;
            #pragma unroll
            for (int j = 0; j < 16; ++j) fma2(a, w2[g][j], h2[j]);
            float lo, hi; unpack2(lo, hi, a);
            s[g] = lo + hi;
        }
        if (k0) {
            #pragma unroll
            for (int g = 0; g < 4; ++g) s[g] += p0[g];
        }
        #pragma unroll
        for (int g = 0; g < 4; ++g) { p0[g] = p1[g]; p1[g] = p2[g]; }

        // ---- butterfly reduce across the 8-lane k-group -------------------
        #pragma unroll
        for (int off = 4; off; off >>= 1) {
            #pragma unroll
            for (int g = 0; g < 4; ++g)
                s[g] += __shfl_xor_sync(0xffffffffu, s[g], off);
        }

        // ---- gating via MUFU.TANH (5 MUFU instead of 10) ------------------
        float iv = sigf(s[0]), fv = sigf(s[1]), ov = sigf(s[3]);
        c = fv * c + iv * tanh_ap(s[2]);
        float h = ov * tanh_ap(c);

        // ---- pack warp's 4 unit h's, publish 16B x 2 ranks per k0 lane ----
        float h0 = __shfl_sync(0xffffffffu, h, 0);
        float h1 = __shfl_sync(0xffffffffu, h, 8);
        float hh2 = __shfl_sync(0xffffffffu, h, 16);
        float h3 = __shfl_sync(0xffffffffu, h, 24);
        if (k0) {
            const int s2 = n & 1;
            ull q0 = pack2(h0, h1), q1 = pack2(hh2, h3);
            st_async_v2b64(remh[s2][0], q0, q1, remb[s2][0]);
            st_async_v2b64(remh[s2][1], q0, q1, remb[s2][1]);
            if (l == 0)
                *(float4*)&hs[(size_t)tstep * HH + ug4] =
                    make_float4(h0, h1, hh2, h3);       // for emit
        }
    }

    mbar_wait(loc_b + ((TT - 1) & 1) * 8, ((TT - 1) >> 1) & 1);
    asm volatile("barrier.cluster.arrive.aligned;" ::: "memory");
    asm volatile("barrier.cluster.wait.aligned;" ::: "memory");
}

// ---------------- fused kernel: 16 lstm CTAs + 256 producer blocks ----------
__global__ void __cluster_dims__(CS, 1, 1) __launch_bounds__(256, 1)
fused_kernel(const int* __restrict__ feats, const float* __restrict__ emb,
             const float* __restrict__ w_ih_f, const float* __restrict__ b_f,
             const float* __restrict__ w_ih_b, const float* __restrict__ b_b,
             const float* __restrict__ w_hh_f, const float* __restrict__ w_hh_b)
{
    if (blockIdx.x < LSTM_BLOCKS)
        lstm_body(w_hh_f, w_hh_b);
    else
        pre_body(blockIdx.x - LSTM_BLOCKS, feats, emb, w_ih_f, b_f, w_ih_b, b_b);
}

// ---------------- emit: [hf|hb] @ W_out.T + b_out --------------------------
__global__ void __launch_bounds__(128) emit_kernel(
    const float* __restrict__ Wo, const float* __restrict__ bo)
{
    const int idx = blockIdx.x * blockDim.x + threadIdx.x;
    if (idx >= TT * LL) return;
    const int t = idx / LL;
    const int l = idx - t * LL;
    const float4* hf = (const float4*)&g_hs[0][(size_t)t * HH];
    const float4* hb = (const float4*)&g_hs[1][(size_t)t * HH];
    const float4* wf = (const float4*)&Wo[(size_t)l * 2 * HH];
    const float4* wb = wf + 64;
    float acc = __ldg(&bo[l]);
    #pragma unroll 8
    for (int k = 0; k < 64; ++k) {
        float4 h4 = __ldg(hf + k), w4 = __ldg(wf + k);
        acc = fmaf(h4.x, w4.x, acc); acc = fmaf(h4.y, w4.y, acc);
        acc = fmaf(h4.z, w4.z, acc); acc = fmaf(h4.w, w4.w, acc);
        float4 h5 = __ldg(hb + k), w5 = __ldg(wb + k);
        acc = fmaf(h5.x, w5.x, acc); acc = fmaf(h5.y, w5.y, acc);
        acc = fmaf(h5.z, w5.z, acc); acc = fmaf(h5.w, w5.w, acc);
    }
    g_emit[idx] = acc;
}

// ---------------- viterbi: warp-specialized + parallel backtrack ------------
#define VRING 256
#define VROWW 20
#define BP_BYTES (TT * LL)                 // 73728
#define OFF_RING BP_BYTES                  // 73728
#define RING_BYTES (VRING * VROWW * 4)     // 20480
#define OFF_CTRL (OFF_RING + RING_BYTES)   // 94208
#define OFF_FMAP (OFF_CTRL + 16)           // 94224
#define NCHUNK 128                         // TT / 32
#define OFF_ENT  (OFF_FMAP + NCHUNK * LL)  // 96528
#define OFF_RES  (OFF_ENT + NCHUNK * 4)    // 97040
#define VIT_SMEM (OFF_RES + 16)            // 97056

__device__ __forceinline__ void vit_load_fv(const float* row, float* sc,
                                            const float* tr) {
    const float4* fr = (const float4*)row;
    float4 f0 = fr[0], f1 = fr[1], f2 = fr[2], f3 = fr[3], f4 = fr[4];
    sc[0]=f0.x+tr[0];  sc[1]=f0.y+tr[1];  sc[2]=f0.z+tr[2];  sc[3]=f0.w+tr[3];
    sc[4]=f1.x+tr[4];  sc[5]=f1.y+tr[5];  sc[6]=f1.z+tr[6];  sc[7]=f1.w+tr[7];
    sc[8]=f2.x+tr[8];  sc[9]=f2.y+tr[9];  sc[10]=f2.z+tr[10]; sc[11]=f2.w+tr[11];
    sc[12]=f3.x+tr[12]; sc[13]=f3.y+tr[13]; sc[14]=f3.z+tr[14]; sc[15]=f3.w+tr[15];
    sc[16]=f4.x+tr[16]; sc[17]=f4.y+tr[17];
}
__device__ __forceinline__ float vit_max18(const float* sc) {
    float m01 = fmaxf(sc[0], sc[1]),   m23 = fmaxf(sc[2], sc[3]);
    float m45 = fmaxf(sc[4], sc[5]),   m67 = fmaxf(sc[6], sc[7]);
    float m89 = fmaxf(sc[8], sc[9]),   mab = fmaxf(sc[10], sc[11]);
    float mcd = fmaxf(sc[12], sc[13]), mef = fmaxf(sc[14], sc[15]);
    float mgh = fmaxf(sc[16], sc[17]);
    float a = fmaxf(fmaxf(m01, m23), fmaxf(m45, m67));
    float b = fmaxf(fmaxf(m89, mab), fmaxf(mcd, mef));
    return fmaxf(fmaxf(a, b), mgh);
}

extern __shared__ unsigned char vit_sh[];
__global__ void __launch_bounds__(128) viterbi_kernel(
    const float* __restrict__ trans, float* __restrict__ out, int out_size)
{
    unsigned char* bp = vit_sh;
    float* fvring = (float*)(vit_sh + OFF_RING);
    int* ctrl = (int*)(vit_sh + OFF_CTRL);
    unsigned char* fmap = vit_sh + OFF_FMAP;
    int* entry = (int*)(vit_sh + OFF_ENT);
    float* res_t = (float*)(vit_sh + OFF_RES);
    int*   res_i = (int*)(vit_sh + OFF_RES + 4);
    const uint32_t wm_a = smem_u32(&ctrl[0]);

    const int tid = threadIdx.x;
    const int w = tid >> 5, l = tid & 31;
    const bool act = l < LL;

    if (tid < 4) ctrl[tid] = 0;
    __syncthreads();

    float tr[LL];
    #pragma unroll
    for (int i = 0; i < LL; ++i) tr[i] = 0.f;
    if (act) {
        #pragma unroll
        for (int i = 0; i < LL; ++i) tr[i] = __ldg(&trans[i * LL + l]);
    }

    if (w == 0) {
        // ------------- fv-chain warp -------------
        float tr_stop = act ? __ldg(&trans[l * LL + STOPL]) : 0.f;
        float fv = (l == STARTL) ? 0.f : NEGV;
        float eb0 = act ? __ldcg(&g_emit[0 * LL + l]) : 0.f;
        float eb1 = act ? __ldcg(&g_emit[1 * LL + l]) : 0.f;
        float eb2 = act ? __ldcg(&g_emit[2 * LL + l]) : 0.f;
        float eb3 = act ? __ldcg(&g_emit[3 * LL + l]) : 0.f;

        for (int t = 0; t < TT; ++t) {
            float* row = &fvring[(t & (VRING - 1)) * VROWW];
            if (act) row[l] = fv;
            __syncwarp();
            float e = eb0;
            eb0 = eb1; eb1 = eb2; eb2 = eb3;
            eb3 = (act && t + 4 < TT) ? __ldcg(&g_emit[(t + 4) * LL + l]) : 0.f;
            float sc[LL];
            vit_load_fv(row, sc, tr);
            fv = vit_max18(sc) + e;

            if ((t & 31) == 31) {
                if (l == 0) {
                    st_rel_sh(wm_a, t + 1);
                    if ((t & (VRING - 1)) == (VRING - 1)) {
                        for (;;) {
                            int m0 = ld_rlx_sh(wm_a + 4);
                            int m1 = ld_rlx_sh(wm_a + 8);
                            int m2 = ld_rlx_sh(wm_a + 12);
                            if (min(m0, min(m1, m2)) >= t - 160) break;
                        }
                    }
                }
                __syncwarp();
            }
        }
        if (l == 0) st_rel_sh(wm_a, TT);

        float term = act ? (fv + tr_stop) : -3.4e38f;
        int bidx = l;
        #pragma unroll
        for (int off = 16; off; off >>= 1) {
            float ov = __shfl_xor_sync(0xffffffffu, term, off);
            int   oi = __shfl_xor_sync(0xffffffffu, bidx, off);
            if (ov > term || (ov == term && oi < bidx)) { term = ov; bidx = oi; }
        }
        if (l == 0) { *res_t = term; *res_i = bidx; }
    } else {
        // ------------- backpointer warps (w = 1..3) -------------
        const uint32_t prog_a = wm_a + 4 * w;
        int wmc = 0, it = 0;
        for (int t = w - 1; t < TT; t += 3, ++it) {
            if (wmc <= t) {
                do { wmc = ld_acq_sh(wm_a); } while (wmc <= t);
            }
            const float* row = &fvring[(t & (VRING - 1)) * VROWW];
            float sc[LL];
            vit_load_fv(row, sc, tr);
            float m = vit_max18(sc);
            unsigned mask = 0;
            #pragma unroll
            for (int i = 0; i < LL; ++i) mask |= (sc[i] == m) ? (1u << i) : 0u;
            int am = __ffs(mask) - 1;
            if (act) bp[t * LL + l] = (unsigned char)am;
            if ((it & 31) == 0 && l == 0) st_rel_sh(prog_a, t);
        }
        if (l == 0) st_rel_sh(prog_a, TT);
    }

    __syncthreads();

    // -------- parallel backtrack: chunk map composition (exact) -----------
    // chunk j covers t in [32j, 32j+31]; F_j = bp[32j] o ... o bp[32j+31]
    {
        const int j = tid;                        // 128 threads = 128 chunks
        const int lo = j * 32, hi = lo + 31;
        int m[LL];
        #pragma unroll
        for (int x = 0; x < LL; ++x) m[x] = bp[hi * LL + x];
        for (int t = hi - 1; t >= lo; --t) {
            const unsigned char* row = &bp[t * LL];
            #pragma unroll
            for (int x = 0; x < LL; ++x) m[x] = row[m[x]];
        }
        #pragma unroll
        for (int x = 0; x < LL; ++x) fmap[j * LL + x] = (unsigned char)m[x];
    }
    __syncthreads();

    if (tid == 0) {                                // serial scan (128 steps)
        int e = *res_i;
        for (int j = NCHUNK - 1; j >= 1; --j) {
            entry[j] = e;
            e = fmap[j * LL + e];
        }
        entry[0] = e;
    }
    __syncthreads();

    {                                              // parallel expansion
        const int off = (out_size > TT) ? 1 : 0;
        const int j = tid;
        const int lo = j * 32, hi = lo + 31;
        int tag = entry[j];
        for (int t = hi; t >= lo; --t) {
            out[off + t] = (float)tag;
            tag = bp[t * LL + tag];
        }
        if (off && tid == 0) out[0] = *res_t;
    }

    // -------- clear producer flags for the next replay ---------------------
    ((int*)g_pflag)[tid] = 0;
    ((int*)g_pflag)[tid + 128] = 0;
}

// ---------------- launch ----------------------------------------------------
extern "C" void kernel_launch(void* const* d_in, const int* in_sizes, int n_in,
                              void* d_out, int out_size)
{
    const int*   feats  = (const int*)d_in[0];
    const float* emb    = (const float*)d_in[1];
    const float* w_ih_f = (const float*)d_in[2];
    const float* w_hh_f = (const float*)d_in[3];
    const float* b_f    = (const float*)d_in[4];
    const float* w_ih_b = (const float*)d_in[5];
    const float* w_hh_b = (const float*)d_in[6];
    const float* b_b    = (const float*)d_in[7];
    const float* W_out  = (const float*)d_in[8];
    const float* b_out  = (const float*)d_in[9];
    const float* trans  = (const float*)d_in[10];
    float* out = (float*)d_out;

    cudaFuncSetAttribute(viterbi_kernel,
                         cudaFuncAttributeMaxDynamicSharedMemorySize, VIT_SMEM);

    fused_kernel<<<LSTM_BLOCKS + PRE_BLOCKS, 256>>>(
        feats, emb, w_ih_f, b_f, w_ih_b, b_b, w_hh_f, w_hh_b);
    emit_kernel<<<(TT * LL + 127) / 128, 128>>>(W_out, b_out);
    viterbi_kernel<<<1, 128, VIT_SMEM>>>(trans, out, out_size);
}

// round 10
// speedup vs baseline: 3.4333x; 3.4333x over previous
#include <cuda_runtime.h>
#include <cuda_bf16.h>
#include <cstdint>

#define TT   4096   // sequence length T
#define EE   256    // embedding dim
#define HH   256    // hidden
#define LL   18     // labels
#define NG   1024   // 4*H gate rows
#define CS   8      // cluster size (CTAs per direction)
#define UPC  32     // hidden units per CTA
#define NEGV -10000.0f
#define STARTL 16
#define STOPL  17
#define TPB  32     // timesteps per pre_gemm block
#define HBUF 288    // padded h buffer: slice k at word 36k (bank spread)
#define IDXH(u) ((u) + ((((unsigned)(u)) >> 5) << 2))

typedef unsigned long long ull;

// ---------------- scratch (static device globals; no runtime alloc) --------
__device__ float g_pre[2][(size_t)TT * NG];   // precomputed x@w_ih.T + b
__device__ float g_hs[2][(size_t)TT * HH];    // hidden states (fwd, bwd)
__device__ float g_emit[(size_t)TT * LL];

// ---------------- helpers --------------------------------------------------
__device__ __forceinline__ float tanh_ap(float x) {        // MUFU.TANH
    float y; asm("tanh.approx.f32 %0, %1;" : "=f"(y) : "f"(x)); return y;
}
__device__ __forceinline__ float sigf(float x) {           // 1 MUFU + 1 FMA
    return fmaf(0.5f, tanh_ap(0.5f * x), 0.5f);
}
__device__ __forceinline__ uint32_t smem_u32(const void* p) {
    uint32_t a;
    asm("{ .reg .u64 t; cvta.to.shared.u64 t, %1; cvt.u32.u64 %0, t; }"
        : "=r"(a) : "l"(p));
    return a;
}
__device__ __forceinline__ uint32_t mapa_rank(uint32_t laddr, uint32_t rank) {
    uint32_t r;
    asm("mapa.shared::cluster.u32 %0, %1, %2;" : "=r"(r) : "r"(laddr), "r"(rank));
    return r;
}
__device__ __forceinline__ void st_async_v2b64(uint32_t raddr, ull a, ull b,
                                               uint32_t rmbar) {
    asm volatile(
        "st.async.shared::cluster.mbarrier::complete_tx::bytes.v2.b64 "
        "[%0], {%1, %2}, [%3];"
        :: "r"(raddr), "l"(a), "l"(b), "r"(rmbar) : "memory");
}
__device__ __forceinline__ void mbar_init(uint32_t addr, uint32_t cnt) {
    asm volatile("mbarrier.init.shared.b64 [%0], %1;" :: "r"(addr), "r"(cnt) : "memory");
}
__device__ __forceinline__ void mbar_expect_tx(uint32_t addr, uint32_t bytes) {
    asm volatile("mbarrier.arrive.expect_tx.shared.b64 _, [%0], %1;"
                 :: "r"(addr), "r"(bytes) : "memory");
}
__device__ __forceinline__ void mbar_wait(uint32_t addr, uint32_t parity) {
    uint32_t done;
    asm volatile(
        "{\n\t.reg .pred p;\n\t"
        "mbarrier.try_wait.parity.acquire.cluster.shared::cta.b64 p, [%1], %2;\n\t"
        "selp.b32 %0, 1, 0, p;\n\t}"
        : "=r"(done) : "r"(addr), "r"(parity) : "memory");
    while (!done) {
        asm volatile(
            "{\n\t.reg .pred p;\n\t"
            "mbarrier.try_wait.parity.acquire.cluster.shared::cta.b64 p, [%1], %2, 0x989680;\n\t"
            "selp.b32 %0, 1, 0, p;\n\t}"
            : "=r"(done) : "r"(addr), "r"(parity) : "memory");
    }
}
__device__ __forceinline__ ull pack2(float x, float y) {
    ull d; asm("mov.b64 %0, {%1, %2};" : "=l"(d) : "f"(x), "f"(y)); return d;
}
__device__ __forceinline__ void unpack2(float& lo, float& hi, ull a) {
    asm("mov.b64 {%0, %1}, %2;" : "=f"(lo), "=f"(hi) : "l"(a));
}
__device__ __forceinline__ void fma2(ull& d, ull a, ull b) {
    asm("fma.rn.f32x2 %0, %1, %2, %0;" : "+l"(d) : "l"(a), "l"(b));
}
__device__ __forceinline__ void st_rel_sh(uint32_t addr, int v) {
    asm volatile("st.release.cta.shared.b32 [%0], %1;" :: "r"(addr), "r"(v) : "memory");
}
__device__ __forceinline__ int ld_acq_sh(uint32_t addr) {
    int v;
    asm volatile("ld.acquire.cta.shared.b32 %0, [%1];" : "=r"(v) : "r"(addr) : "memory");
    return v;
}
__device__ __forceinline__ int ld_rlx_sh(uint32_t addr) {
    int v;
    asm volatile("ld.relaxed.cta.shared.b32 %0, [%1];" : "=r"(v) : "r"(addr) : "memory");
    return v;
}

// ---------------- pre-GEMM: pre[d][t][row] = emb[feat[t]] . w_ih[row] + b --
__global__ void __launch_bounds__(256) pre_gemm_kernel(
    const int* __restrict__ feats, const float* __restrict__ emb,
    const float* __restrict__ w_f, const float* __restrict__ b_f,
    const float* __restrict__ w_b, const float* __restrict__ b_b)
{
    __shared__ float xs[TPB][EE];
    const int tid = threadIdx.x;
    const int dir = blockIdx.y;
    const int t0  = blockIdx.x * TPB;
    const float* w  = dir ? w_b : w_f;
    const float* bb = dir ? b_b : b_f;
    float* pre = g_pre[dir];

    {
        int i = tid >> 3, c = tid & 7;
        int f = feats[t0 + i];
        const float4* src = (const float4*)(emb + (size_t)f * EE);
        #pragma unroll
        for (int cc = 0; cc < 8; ++cc)
            ((float4*)xs[i])[c + cc * 8] = __ldg(src + c + cc * 8);
    }
    __syncthreads();

    for (int q = 0; q < 4; ++q) {
        const int row = q * 256 + tid;
        const float4* wp = (const float4*)(w + (size_t)row * EE);
        const float bv = __ldg(&bb[row]);
        float acc[TPB];
        #pragma unroll
        for (int i = 0; i < TPB; ++i) acc[i] = bv;
        for (int k4 = 0; k4 < 64; ++k4) {
            float4 wv = __ldg(wp + k4);
            #pragma unroll
            for (int i = 0; i < TPB; ++i) {
                float4 xv = *(const float4*)&xs[i][k4 * 4];
                acc[i] = fmaf(wv.x, xv.x, acc[i]);
                acc[i] = fmaf(wv.y, xv.y, acc[i]);
                acc[i] = fmaf(wv.z, xv.z, acc[i]);
                acc[i] = fmaf(wv.w, xv.w, acc[i]);
            }
        }
        #pragma unroll
        for (int i = 0; i < TPB; ++i)
            pre[(size_t)(t0 + i) * NG + row] = acc[i];
    }
}

// ---------------- persistent LSTM: 2 clusters of 8 CTAs ---------------------
// R6/R8 tiling (crossbar-aware): thread = (unit, k-slice); kq = l&7 picks a
// 32-float h slice, lanes {l,l+8,l+16,l+24} read identical smem (broadcast).
// Single aggregate barrier per parity. Publish = 16B st.async.v2.b64, 4
// k0-lanes x 2 ranks. Gating via MUFU.TANH (5 MUFU/step instead of 10).
__global__ void __cluster_dims__(CS, 1, 1) __launch_bounds__(256, 1)
lstm_kernel(const float* __restrict__ whh_f, const float* __restrict__ whh_b)
{
    __shared__ __align__(16) float sh_h[2][HBUF];
    __shared__ ull smbar[2];

    const int tid = threadIdx.x;
    const int dir = blockIdx.x / CS;
    uint32_t rank;
    asm("mov.u32 %0, %%cluster_ctarank;" : "=r"(rank));

    const int w = tid >> 5, l = tid & 31;
    const int kq   = l & 7;                 // k-slice: h[kq*32 .. +32)
    const int ugrp = w * 4 + (l >> 3);      // unit local 0..31
    const int unit_global = (int)rank * UPC + ugrp;
    const bool k0 = (kq == 0);
    const int ug4 = (int)rank * UPC + w * 4;   // warp's 4-unit group base

    // weights: 4 gate rows of this unit, cols [kq*32, +32) as f32x2 pairs
    const float* whh = dir ? whh_b : whh_f;
    ull w2[4][16];
    #pragma unroll
    for (int g = 0; g < 4; ++g) {
        const float4* wp = (const float4*)(whh + (size_t)(g * HH + unit_global) * HH + kq * 32);
        #pragma unroll
        for (int m = 0; m < 8; ++m) {
            float4 f = __ldg(wp + m);
            w2[g][2 * m]     = pack2(f.x, f.y);
            w2[g][2 * m + 1] = pack2(f.z, f.w);
        }
    }

    // publish targets: k0 lane (l>>3 = j) sends warp's 16B group to 2 ranks
    const int j2 = (l >> 3) * 2;
    const uint32_t loc_b = smem_u32(&smbar[0]);
    uint32_t remh[2][2], remb[2][2];
    #pragma unroll
    for (int s = 0; s < 2; ++s) {
        const uint32_t locp = smem_u32(&sh_h[s][IDXH(ug4)]);
        #pragma unroll
        for (int i = 0; i < 2; ++i) {
            remh[s][i] = mapa_rank(locp, j2 + i);
            remb[s][i] = mapa_rank(loc_b + s * 8, j2 + i);
        }
    }

    for (int i = tid; i < 2 * HBUF; i += 256) ((float*)sh_h)[i] = 0.f;
    if (tid == 0) { mbar_init(loc_b, 1); mbar_init(loc_b + 8, 1); }
    __syncthreads();
    asm volatile("barrier.cluster.arrive.aligned;" ::: "memory");
    asm volatile("barrier.cluster.wait.aligned;" ::: "memory");

    const float* pre = g_pre[dir];
    float* hs = g_hs[dir];
    float c = 0.f;

    auto tmap = [&](int n) { return dir ? (TT - 1 - n) : n; };
    float p0[4], p1[4];
    #pragma unroll
    for (int g = 0; g < 4; ++g) { p0[g] = 0.f; p1[g] = 0.f; }
    if (k0) {
        #pragma unroll
        for (int g = 0; g < 4; ++g) {
            p0[g] = __ldcg(&pre[(size_t)tmap(0) * NG + g * HH + unit_global]);
            p1[g] = __ldcg(&pre[(size_t)tmap(1) * NG + g * HH + unit_global]);
        }
    }

    for (int n = 0; n < TT; ++n) {
        const int tstep = tmap(n);
        if (tid == 0) mbar_expect_tx(loc_b + (n & 1) * 8, CS * UPC * 4);
        if (n > 0) mbar_wait(loc_b + ((n - 1) & 1) * 8, ((n - 1) >> 1) & 1);

        float p2[4] = {0.f, 0.f, 0.f, 0.f};
        if (k0 && n + 2 < TT) {
            #pragma unroll
            for (int g = 0; g < 4; ++g)
                p2[g] = __ldcg(&pre[(size_t)tmap(n + 2) * NG + g * HH + unit_global]);
        }

        // ---- load my 32-float h slice (broadcast x4 across lanes) ---------
        const ulonglong2* hp =
            (const ulonglong2*)((const char*)sh_h[(n + 1) & 1] + kq * 144);
        ull h2[16];
        #pragma unroll
        for (int j = 0; j < 8; ++j) {
            ulonglong2 v = hp[j];
            h2[2 * j] = v.x; h2[2 * j + 1] = v.y;
        }

        // ---- 4 gate partial dots over the slice ---------------------------
        float s[4];
        #pragma unroll
        for (int g = 0; g < 4; ++g) {
            ull a = 0ull;
            #pragma unroll
            for (int j = 0; j < 16; ++j) fma2(a, w2[g][j], h2[j]);
            float lo, hi; unpack2(lo, hi, a);
            s[g] = lo + hi;
        }
        if (k0) {
            #pragma unroll
            for (int g = 0; g < 4; ++g) s[g] += p0[g];
        }
        #pragma unroll
        for (int g = 0; g < 4; ++g) { p0[g] = p1[g]; p1[g] = p2[g]; }

        // ---- butterfly reduce across the 8-lane k-group -------------------
        #pragma unroll
        for (int off = 4; off; off >>= 1) {
            #pragma unroll
            for (int g = 0; g < 4; ++g)
                s[g] += __shfl_xor_sync(0xffffffffu, s[g], off);
        }

        // ---- gating via MUFU.TANH (5 MUFU instead of 10) ------------------
        float iv = sigf(s[0]), fv = sigf(s[1]), ov = sigf(s[3]);
        c = fv * c + iv * tanh_ap(s[2]);
        float h = ov * tanh_ap(c);

        // ---- pack warp's 4 unit h's, publish 16B x 2 ranks per k0 lane ----
        float h0 = __shfl_sync(0xffffffffu, h, 0);
        float h1 = __shfl_sync(0xffffffffu, h, 8);
        float hh2 = __shfl_sync(0xffffffffu, h, 16);
        float h3 = __shfl_sync(0xffffffffu, h, 24);
        if (k0) {
            const int s2 = n & 1;
            ull q0 = pack2(h0, h1), q1 = pack2(hh2, h3);
            st_async_v2b64(remh[s2][0], q0, q1, remb[s2][0]);
            st_async_v2b64(remh[s2][1], q0, q1, remb[s2][1]);
            if (l == 0)
                *(float4*)&hs[(size_t)tstep * HH + ug4] =
                    make_float4(h0, h1, hh2, h3);       // for emit
        }
    }

    mbar_wait(loc_b + ((TT - 1) & 1) * 8, ((TT - 1) >> 1) & 1);
    asm volatile("barrier.cluster.arrive.aligned;" ::: "memory");
    asm volatile("barrier.cluster.wait.aligned;" ::: "memory");
}

// ---------------- emit: [hf|hb] @ W_out.T + b_out --------------------------
__global__ void __launch_bounds__(128) emit_kernel(
    const float* __restrict__ Wo, const float* __restrict__ bo)
{
    const int idx = blockIdx.x * blockDim.x + threadIdx.x;
    if (idx >= TT * LL) return;
    const int t = idx / LL;
    const int l = idx - t * LL;
    const float4* hf = (const float4*)&g_hs[0][(size_t)t * HH];
    const float4* hb = (const float4*)&g_hs[1][(size_t)t * HH];
    const float4* wf = (const float4*)&Wo[(size_t)l * 2 * HH];
    const float4* wb = wf + 64;
    float acc = __ldg(&bo[l]);
    #pragma unroll 8
    for (int k = 0; k < 64; ++k) {
        float4 h4 = __ldg(hf + k), w4 = __ldg(wf + k);
        acc = fmaf(h4.x, w4.x, acc); acc = fmaf(h4.y, w4.y, acc);
        acc = fmaf(h4.z, w4.z, acc); acc = fmaf(h4.w, w4.w, acc);
        float4 h5 = __ldg(hb + k), w5 = __ldg(wb + k);
        acc = fmaf(h5.x, w5.x, acc); acc = fmaf(h5.y, w5.y, acc);
        acc = fmaf(h5.z, w5.z, acc); acc = fmaf(h5.w, w5.w, acc);
    }
    g_emit[idx] = acc;
}

// ---------------- viterbi: warp-specialized + parallel backtrack ------------
#define VRING 256
#define VROWW 20
#define BP_BYTES (TT * LL)                 // 73728
#define OFF_RING BP_BYTES
#define RING_BYTES (VRING * VROWW * 4)     // 20480
#define OFF_CTRL (OFF_RING + RING_BYTES)
#define OFF_FMAP (OFF_CTRL + 16)
#define NCHUNK 128                         // TT / 32
#define OFF_ENT  (OFF_FMAP + NCHUNK * LL)
#define OFF_RES  (OFF_ENT + NCHUNK * 4)
#define VIT_SMEM (OFF_RES + 16)

__device__ __forceinline__ void vit_load_fv(const float* row, float* sc,
                                            const float* tr) {
    const float4* fr = (const float4*)row;
    float4 f0 = fr[0], f1 = fr[1], f2 = fr[2], f3 = fr[3], f4 = fr[4];
    sc[0]=f0.x+tr[0];  sc[1]=f0.y+tr[1];  sc[2]=f0.z+tr[2];  sc[3]=f0.w+tr[3];
    sc[4]=f1.x+tr[4];  sc[5]=f1.y+tr[5];  sc[6]=f1.z+tr[6];  sc[7]=f1.w+tr[7];
    sc[8]=f2.x+tr[8];  sc[9]=f2.y+tr[9];  sc[10]=f2.z+tr[10]; sc[11]=f2.w+tr[11];
    sc[12]=f3.x+tr[12]; sc[13]=f3.y+tr[13]; sc[14]=f3.z+tr[14]; sc[15]=f3.w+tr[15];
    sc[16]=f4.x+tr[16]; sc[17]=f4.y+tr[17];
}
__device__ __forceinline__ float vit_max18(const float* sc) {
    float m01 = fmaxf(sc[0], sc[1]),   m23 = fmaxf(sc[2], sc[3]);
    float m45 = fmaxf(sc[4], sc[5]),   m67 = fmaxf(sc[6], sc[7]);
    float m89 = fmaxf(sc[8], sc[9]),   mab = fmaxf(sc[10], sc[11]);
    float mcd = fmaxf(sc[12], sc[13]), mef = fmaxf(sc[14], sc[15]);
    float mgh = fmaxf(sc[16], sc[17]);
    float a = fmaxf(fmaxf(m01, m23), fmaxf(m45, m67));
    float b = fmaxf(fmaxf(m89, mab), fmaxf(mcd, mef));
    return fmaxf(fmaxf(a, b), mgh);
}

extern __shared__ unsigned char vit_sh[];
__global__ void __launch_bounds__(128) viterbi_kernel(
    const float* __restrict__ trans, float* __restrict__ out, int out_size)
{
    unsigned char* bp = vit_sh;
    float* fvring = (float*)(vit_sh + OFF_RING);
    int* ctrl = (int*)(vit_sh + OFF_CTRL);
    unsigned char* fmap = vit_sh + OFF_FMAP;
    int* entry = (int*)(vit_sh + OFF_ENT);
    float* res_t = (float*)(vit_sh + OFF_RES);
    int*   res_i = (int*)(vit_sh + OFF_RES + 4);
    const uint32_t wm_a = smem_u32(&ctrl[0]);

    const int tid = threadIdx.x;
    const int w = tid >> 5, l = tid & 31;
    const bool act = l < LL;

    if (tid < 4) ctrl[tid] = 0;
    __syncthreads();

    float tr[LL];
    #pragma unroll
    for (int i = 0; i < LL; ++i) tr[i] = 0.f;
    if (act) {
        #pragma unroll
        for (int i = 0; i < LL; ++i) tr[i] = __ldg(&trans[i * LL + l]);
    }

    if (w == 0) {
        // ------------- fv-chain warp -------------
        float tr_stop = act ? __ldg(&trans[l * LL + STOPL]) : 0.f;
        float fv = (l == STARTL) ? 0.f : NEGV;
        float eb0 = act ? __ldcg(&g_emit[0 * LL + l]) : 0.f;
        float eb1 = act ? __ldcg(&g_emit[1 * LL + l]) : 0.f;
        float eb2 = act ? __ldcg(&g_emit[2 * LL + l]) : 0.f;
        float eb3 = act ? __ldcg(&g_emit[3 * LL + l]) : 0.f;

        for (int t = 0; t < TT; ++t) {
            float* row = &fvring[(t & (VRING - 1)) * VROWW];
            if (act) row[l] = fv;
            __syncwarp();
            float e = eb0;
            eb0 = eb1; eb1 = eb2; eb2 = eb3;
            eb3 = (act && t + 4 < TT) ? __ldcg(&g_emit[(t + 4) * LL + l]) : 0.f;
            float sc[LL];
            vit_load_fv(row, sc, tr);
            fv = vit_max18(sc) + e;

            if ((t & 31) == 31) {
                if (l == 0) {
                    st_rel_sh(wm_a, t + 1);
                    if ((t & (VRING - 1)) == (VRING - 1)) {
                        for (;;) {
                            int m0 = ld_rlx_sh(wm_a + 4);
                            int m1 = ld_rlx_sh(wm_a + 8);
                            int m2 = ld_rlx_sh(wm_a + 12);
                            if (min(m0, min(m1, m2)) >= t - 160) break;
                        }
                    }
                }
                __syncwarp();
            }
        }
        if (l == 0) st_rel_sh(wm_a, TT);

        float term = act ? (fv + tr_stop) : -3.4e38f;
        int bidx = l;
        #pragma unroll
        for (int off = 16; off; off >>= 1) {
            float ov = __shfl_xor_sync(0xffffffffu, term, off);
            int   oi = __shfl_xor_sync(0xffffffffu, bidx, off);
            if (ov > term || (ov == term && oi < bidx)) { term = ov; bidx = oi; }
        }
        if (l == 0) { *res_t = term; *res_i = bidx; }
    } else {
        // ------------- backpointer warps (w = 1..3) -------------
        const uint32_t prog_a = wm_a + 4 * w;
        int wmc = 0, it = 0;
        for (int t = w - 1; t < TT; t += 3, ++it) {
            if (wmc <= t) {
                do { wmc = ld_acq_sh(wm_a); } while (wmc <= t);
            }
            const float* row = &fvring[(t & (VRING - 1)) * VROWW];
            float sc[LL];
            vit_load_fv(row, sc, tr);
            float m = vit_max18(sc);
            unsigned mask = 0;
            #pragma unroll
            for (int i = 0; i < LL; ++i) mask |= (sc[i] == m) ? (1u << i) : 0u;
            int am = __ffs(mask) - 1;
            if (act) bp[t * LL + l] = (unsigned char)am;
            if ((it & 31) == 0 && l == 0) st_rel_sh(prog_a, t);
        }
        if (l == 0) st_rel_sh(prog_a, TT);
    }

    __syncthreads();

    // -------- parallel backtrack: chunk map composition (exact) -----------
    {
        const int j = tid;                        // 128 threads = 128 chunks
        const int lo = j * 32, hi = lo + 31;
        int m[LL];
        #pragma unroll
        for (int x = 0; x < LL; ++x) m[x] = bp[hi * LL + x];
        for (int t = hi - 1; t >= lo; --t) {
            const unsigned char* row = &bp[t * LL];
            #pragma unroll
            for (int x = 0; x < LL; ++x) m[x] = row[m[x]];
        }
        #pragma unroll
        for (int x = 0; x < LL; ++x) fmap[j * LL + x] = (unsigned char)m[x];
    }
    __syncthreads();

    if (tid == 0) {                                // serial scan (128 chunks)
        int e = *res_i;
        for (int j = NCHUNK - 1; j >= 1; --j) {
            entry[j] = e;
            e = fmap[j * LL + e];
        }
        entry[0] = e;
    }
    __syncthreads();

    {                                              // parallel expansion
        const int off = (out_size > TT) ? 1 : 0;
        const int j = tid;
        const int lo = j * 32, hi = lo + 31;
        int tag = entry[j];
        for (int t = hi; t >= lo; --t) {
            out[off + t] = (float)tag;
            tag = bp[t * LL + tag];
        }
        if (off && tid == 0) out[0] = *res_t;
    }
}

// ---------------- launch ----------------------------------------------------
extern "C" void kernel_launch(void* const* d_in, const int* in_sizes, int n_in,
                              void* d_out, int out_size)
{
    const int*   feats  = (const int*)d_in[0];
    const float* emb    = (const float*)d_in[1];
    const float* w_ih_f = (const float*)d_in[2];
    const float* w_hh_f = (const float*)d_in[3];
    const float* b_f    = (const float*)d_in[4];
    const float* w_ih_b = (const float*)d_in[5];
    const float* w_hh_b = (const float*)d_in[6];
    const float* b_b    = (const float*)d_in[7];
    const float* W_out  = (const float*)d_in[8];
    const float* b_out  = (const float*)d_in[9];
    const float* trans  = (const float*)d_in[10];
    float* out = (float*)d_out;

    cudaFuncSetAttribute(viterbi_kernel,
                         cudaFuncAttributeMaxDynamicSharedMemorySize, VIT_SMEM);

    pre_gemm_kernel<<<dim3(TT / TPB, 2), 256>>>(feats, emb, w_ih_f, b_f, w_ih_b, b_b);
    lstm_kernel<<<2 * CS, 256>>>(w_hh_f, w_hh_b);
    emit_kernel<<<(TT * LL + 127) / 128, 128>>>(W_out, b_out);
    viterbi_kernel<<<1, 128, VIT_SMEM>>>(trans, out, out_size);
}